// round 5
// baseline (speedup 1.0000x reference)
#include <cuda_runtime.h>

// Problem constants
#define LL 8
#define KK 8
#define NN 1048576
#define NVEC  (NN / 4)         // 262144 float4 per (l,k) row (apply)
#define NVEC2 (NN / 2)         // 524288 float2 per (l,k) row (gram)
#define NPAIR 36               // triangular 8x8
#define GX 256                 // gram blocks per layer
#define AX 256                 // apply blocks per layer

// Scratch (allocation-free rule: __device__ globals)
// Partial Gram sums, layout [l][pair][block] so the reducer reads contiguous.
__device__ float4 g_partial4[LL * NPAIR * GX / 4];   // 288 KB
__device__ float  g_W[LL * KK * KK];                  // 512 floats

// triangular index for a<=b
__host__ __device__ __forceinline__ int tri_idx(int a, int b) {
    return a * KK - (a * (a - 1)) / 2 + (b - a);
}

// ---------------------------------------------------------------------------
// Kernel 1: Gram partial sums. grid = (GX, L), block = 256.
// float2 loads (register diet -> 4 CTAs/SM, 32 warps). Default cache policy
// so deltas' tail stays resident in L2 for the apply kernel.
// ---------------------------------------------------------------------------
__global__ void __launch_bounds__(256, 4)
gram_kernel(const float* __restrict__ deltas) {
    const int l = blockIdx.y;
    const float2* __restrict__ base =
        reinterpret_cast<const float2*>(deltas) + (size_t)l * KK * NVEC2;

    float acc[NPAIR];
#pragma unroll
    for (int p = 0; p < NPAIR; ++p) acc[p] = 0.0f;

    const int stride = GX * 256;
    for (int i = blockIdx.x * 256 + threadIdx.x; i < NVEC2; i += stride) {
        float2 v[KK];
#pragma unroll
        for (int j = 0; j < KK; ++j) v[j] = base[(size_t)j * NVEC2 + i];
        int p = 0;
#pragma unroll
        for (int a = 0; a < KK; ++a) {
#pragma unroll
            for (int b = a; b < KK; ++b) {
                acc[p] = fmaf(v[a].x, v[b].x, acc[p]);
                acc[p] = fmaf(v[a].y, v[b].y, acc[p]);
                ++p;
            }
        }
    }

    // warp reduce each accumulator, then cross-warp via smem
    __shared__ float sred[8][NPAIR];
    const int lane = threadIdx.x & 31;
    const int wid  = threadIdx.x >> 5;
#pragma unroll
    for (int p = 0; p < NPAIR; ++p) {
        float v = acc[p];
#pragma unroll
        for (int o = 16; o > 0; o >>= 1) v += __shfl_down_sync(0xffffffffu, v, o);
        if (lane == 0) sred[wid][p] = v;
    }
    __syncthreads();

    if (threadIdx.x < NPAIR) {
        float s = 0.0f;
#pragma unroll
        for (int w = 0; w < 8; ++w) s += sred[w][threadIdx.x];
        float* pf = reinterpret_cast<float*>(g_partial4);
        pf[((size_t)l * NPAIR + threadIdx.x) * GX + blockIdx.x] = s;
    }
}

// ---------------------------------------------------------------------------
// Kernel 2: reduce partials + softmax + build W = I + clip(beta)*attn.
// <<<1, 288>>>
// ---------------------------------------------------------------------------
__global__ void softmax_kernel(const float* __restrict__ beta) {
    __shared__ float tri[LL * NPAIR];
    const int t = threadIdx.x;

    if (t < LL * NPAIR) {
        const float4* __restrict__ p = &g_partial4[(size_t)t * (GX / 4)];
        float sx = 0.f, sy = 0.f, sz = 0.f, sw = 0.f;
#pragma unroll 8
        for (int g = 0; g < GX / 4; ++g) {
            float4 v = p[g];
            sx += v.x; sy += v.y; sz += v.z; sw += v.w;
        }
        tri[t] = (sx + sy) + (sz + sw);
    }
    __syncthreads();

    if (t < LL * KK) {
        const int l = t >> 3, k = t & 7;
        const float scale = rsqrtf((float)NN);
        float v[KK];
        float m = -1e30f;
#pragma unroll
        for (int j = 0; j < KK; ++j) {
            int a = k < j ? k : j;
            int b = k < j ? j : k;
            v[j] = tri[l * NPAIR + tri_idx(a, b)] * scale;
            m = fmaxf(m, v[j]);
        }
        float s = 0.0f;
#pragma unroll
        for (int j = 0; j < KK; ++j) {
            v[j] = __expf(v[j] - m);
            s += v[j];
        }
        float inv = 1.0f / s;
        float bcl = fminf(fmaxf(beta[l * KK + k], 0.0f), 1.0f);
#pragma unroll
        for (int j = 0; j < KK; ++j) {
            g_W[l * KK * KK + k * KK + j] =
                bcl * v[j] * inv + ((j == k) ? 1.0f : 0.0f);
        }
    }
}

// ---------------------------------------------------------------------------
// Kernel 3: out[l,k,:] = last[l,k,:] + sum_j W[l,k,j] * deltas[l,j,:]
// REVERSE traversal: highest indices first, to hit the deltas tail that
// gram_kernel left resident in L2. deltas: default (L2 lookup);
// last: __ldcs evict-first; out: __stcs evict-first.
// ---------------------------------------------------------------------------
__global__ void __launch_bounds__(256, 3)
apply_kernel(const float* __restrict__ last,
             const float* __restrict__ deltas,
             float* __restrict__ out) {
    const int l = blockIdx.y;
    __shared__ float W[KK * KK];
    if (threadIdx.x < KK * KK) W[threadIdx.x] = g_W[l * KK * KK + threadIdx.x];
    __syncthreads();

    const float4* __restrict__ d4 =
        reinterpret_cast<const float4*>(deltas) + (size_t)l * KK * NVEC;
    const float4* __restrict__ p4 =
        reinterpret_cast<const float4*>(last) + (size_t)l * KK * NVEC;
    float4* __restrict__ o4 =
        reinterpret_cast<float4*>(out) + (size_t)l * KK * NVEC;

    const int stride = AX * 256;
    // reverse chunk order: start from the highest chunk this thread owns
    const int base_i = blockIdx.x * 256 + threadIdx.x;
    const int nchunks = (NVEC - base_i + stride - 1) / stride;   // = 4 here
    for (int c = nchunks - 1; c >= 0; --c) {
        const int i = base_i + c * stride;
        float4 acc[KK];
#pragma unroll
        for (int k = 0; k < KK; ++k) acc[k] = __ldcs(&p4[(size_t)k * NVEC + i]);
#pragma unroll
        for (int j = 0; j < KK; ++j) {
            float4 v = d4[(size_t)j * NVEC + i];
#pragma unroll
            for (int k = 0; k < KK; ++k) {
                float w = W[k * KK + j];
                acc[k].x = fmaf(w, v.x, acc[k].x);
                acc[k].y = fmaf(w, v.y, acc[k].y);
                acc[k].z = fmaf(w, v.z, acc[k].z);
                acc[k].w = fmaf(w, v.w, acc[k].w);
            }
        }
#pragma unroll
        for (int k = 0; k < KK; ++k) __stcs(&o4[(size_t)k * NVEC + i], acc[k]);
    }
}

// ---------------------------------------------------------------------------
extern "C" void kernel_launch(void* const* d_in, const int* in_sizes, int n_in,
                              void* d_out, int out_size) {
    const float* last_params = (const float*)d_in[0];
    const float* deltas      = (const float*)d_in[1];
    const float* beta        = (const float*)d_in[2];
    float* out               = (float*)d_out;

    gram_kernel<<<dim3(GX, LL), 256>>>(deltas);
    softmax_kernel<<<1, 288>>>(beta);
    apply_kernel<<<dim3(AX, LL), 256>>>(last_params, deltas, out);
}

// round 7
// speedup vs baseline: 1.1595x; 1.1595x over previous
#include <cuda_runtime.h>

// Problem constants
#define LL 8
#define KK 8
#define NN 1048576
#define NVEC (NN / 4)          // 262144 float4 per (l,k) row
#define NPAIR 36               // triangular 8x8
#define NSM 148
#define OCC 2
#define NCTA (NSM * OCC)       // 296 CTAs, all resident (2/SM guaranteed)
#define THREADS 256
#define PAD 32                 // pad tri entries to separate 128B lines (LTS spread)

// Scratch (allocation-free rule: __device__ globals)
__device__ float    g_tri[LL][NPAIR * PAD];   // padded triangular Gram sums
__device__ unsigned g_bar;                     // grid barrier counter

__device__ __forceinline__ int tri_idx(int a, int b) {
    return a * KK - (a * (a - 1)) / 2 + (b - a);
}

// ---------------------------------------------------------------------------
// Init: reset barrier counter + zero tri accumulators (every replay)
// ---------------------------------------------------------------------------
__global__ void init_kernel() {
    const int t = threadIdx.x;
    if (t == 0) g_bar = 0u;
    float* p = reinterpret_cast<float*>(g_tri);
    for (int i = t; i < LL * NPAIR * PAD; i += blockDim.x) p[i] = 0.0f;
}

// ---------------------------------------------------------------------------
// Software grid barrier: monotonic targets, CG-style fencing.
// Safe because all NCTA CTAs are co-resident (__launch_bounds__ enforced).
// ---------------------------------------------------------------------------
__device__ __forceinline__ void grid_barrier(unsigned target) {
    __threadfence();            // each thread's prior atomics/stores visible
    __syncthreads();            // all threads of CTA done before arrival
    if (threadIdx.x == 0) {
        atomicAdd(&g_bar, 1u);
        while (*(volatile unsigned*)&g_bar < target) __nanosleep(64);
    }
    __syncthreads();
    __threadfence();
}

// ---------------------------------------------------------------------------
// Persistent fused kernel: per layer {gram -> barrier -> softmax -> apply}.
// deltas[l] (32 MB) stays L2-resident between gram and apply phases, cutting
// DRAM traffic from 1074 MB to 768 MB.
// ---------------------------------------------------------------------------
__global__ void __launch_bounds__(THREADS, OCC)
fused_kernel(const float* __restrict__ last,
             const float* __restrict__ deltas,
             const float* __restrict__ beta,
             float* __restrict__ out) {
    const int tid  = threadIdx.x;
    const int cta  = blockIdx.x;
    const int lane = tid & 31;
    const int wid  = tid >> 5;

    __shared__ float sred[8][NPAIR];
    __shared__ float Ws[KK * KK];

    for (int l = 0; l < LL; ++l) {
        const float4* __restrict__ d4 =
            reinterpret_cast<const float4*>(deltas) + (size_t)l * KK * NVEC;
        const float4* __restrict__ p4 =
            reinterpret_cast<const float4*>(last) + (size_t)l * KK * NVEC;
        float4* __restrict__ o4 =
            reinterpret_cast<float4*>(out) + (size_t)l * KK * NVEC;

        // ---------------- Phase 1: Gram over this CTA's slice ----------------
        float acc[NPAIR];
#pragma unroll
        for (int p = 0; p < NPAIR; ++p) acc[p] = 0.0f;

        for (int i = cta * THREADS + tid; i < NVEC; i += NCTA * THREADS) {
            float4 v[KK];
#pragma unroll
            for (int j = 0; j < KK; ++j) v[j] = d4[(size_t)j * NVEC + i];
            int p = 0;
#pragma unroll
            for (int a = 0; a < KK; ++a) {
#pragma unroll
                for (int b = a; b < KK; ++b) {
                    acc[p] = fmaf(v[a].x, v[b].x, acc[p]);
                    acc[p] = fmaf(v[a].y, v[b].y, acc[p]);
                    acc[p] = fmaf(v[a].z, v[b].z, acc[p]);
                    acc[p] = fmaf(v[a].w, v[b].w, acc[p]);
                    ++p;
                }
            }
        }

        // warp reduce, then cross-warp via smem
#pragma unroll
        for (int p = 0; p < NPAIR; ++p) {
            float v = acc[p];
#pragma unroll
            for (int o = 16; o > 0; o >>= 1)
                v += __shfl_down_sync(0xffffffffu, v, o);
            if (lane == 0) sred[wid][p] = v;
        }
        __syncthreads();
        if (tid < NPAIR) {
            float s = 0.0f;
#pragma unroll
            for (int w = 0; w < 8; ++w) s += sred[w][tid];
            atomicAdd(&g_tri[l][tid * PAD], s);   // padded: distinct 128B lines
        }

        // ---------------- Grid barrier: all Gram contributions in ----------------
        grid_barrier((unsigned)((l + 1) * NCTA));

        // ---------------- Phase 2: per-CTA softmax -> W in smem ----------------
        if (tid < KK) {
            const int k = tid;
            const float scale = rsqrtf((float)NN);
            float v[KK];
            float m = -1e30f;
#pragma unroll
            for (int j = 0; j < KK; ++j) {
                int a = k < j ? k : j;
                int b = k < j ? j : k;
                v[j] = g_tri[l][tri_idx(a, b) * PAD] * scale;
                m = fmaxf(m, v[j]);
            }
            float s = 0.0f;
#pragma unroll
            for (int j = 0; j < KK; ++j) {
                v[j] = __expf(v[j] - m);
                s += v[j];
            }
            float inv = 1.0f / s;
            float bcl = fminf(fmaxf(beta[l * KK + k], 0.0f), 1.0f);
#pragma unroll
            for (int j = 0; j < KK; ++j)
                Ws[k * KK + j] = bcl * v[j] * inv + ((j == k) ? 1.0f : 0.0f);
        }
        __syncthreads();

        // ---------------- Phase 3: apply (deltas hit L2) ----------------
        for (int i = cta * THREADS + tid; i < NVEC; i += NCTA * THREADS) {
            float4 oacc[KK];
#pragma unroll
            for (int k = 0; k < KK; ++k)
                oacc[k] = __ldcs(&p4[(size_t)k * NVEC + i]);   // evict-first
#pragma unroll
            for (int j = 0; j < KK; ++j) {
                float4 v = d4[(size_t)j * NVEC + i];           // L2-resident
#pragma unroll
                for (int k = 0; k < KK; ++k) {
                    float w = Ws[k * KK + j];
                    oacc[k].x = fmaf(w, v.x, oacc[k].x);
                    oacc[k].y = fmaf(w, v.y, oacc[k].y);
                    oacc[k].z = fmaf(w, v.z, oacc[k].z);
                    oacc[k].w = fmaf(w, v.w, oacc[k].w);
                }
            }
#pragma unroll
            for (int k = 0; k < KK; ++k)
                __stcs(&o4[(size_t)k * NVEC + i], oacc[k]);    // evict-first
        }
        // no barrier needed here: next layer touches disjoint g_tri[l+1],
        // and its read is guarded by grid_barrier(l+2).
    }
}

// ---------------------------------------------------------------------------
extern "C" void kernel_launch(void* const* d_in, const int* in_sizes, int n_in,
                              void* d_out, int out_size) {
    const float* last_params = (const float*)d_in[0];
    const float* deltas      = (const float*)d_in[1];
    const float* beta        = (const float*)d_in[2];
    float* out               = (float*)d_out;

    init_kernel<<<1, 1024>>>();
    fused_kernel<<<NCTA, THREADS>>>(last_params, deltas, beta, out);
}